// round 1
// baseline (speedup 1.0000x reference)
#include <cuda_runtime.h>
#include <math.h>

// Problem constants (fixed by setup_inputs)
#define BSZ    2
#define LSEQ   1024
#define HDIM   2048
#define DDIM   4096
#define NSTATE 16
#define RRANK  128
#define KCONV  4
#define BL     (BSZ * LSEQ)          // 2048 rows
#define P2D    (2 * DDIM)            // 8192
#define SP_W   (RRANK + 2 * NSTATE)  // 160

// ---------------------------------------------------------------------------
// Scratch (no cudaMalloc allowed): static device globals, ~170 MB total
// ---------------------------------------------------------------------------
__device__ float g_proj[(size_t)BL * P2D];   // in_proj output [BL, 8192] (u | gate)
__device__ float g_u  [(size_t)BL * DDIM];   // conv+silu output [BL, D]
__device__ float g_sp [(size_t)BL * SP_W];   // x_proj output [BL, 160]
__device__ float g_dt [(size_t)BL * DDIM];   // softplus(dt_proj) [BL, D]
__device__ float g_y  [(size_t)BL * DDIM];   // scan output (gated) [BL, D]

__device__ __forceinline__ float softplusf(float x) {
    return (x > 20.f) ? x : log1pf(__expf(x));
}
__device__ __forceinline__ float siluf(float x) {
    return x / (1.f + __expf(-x));
}

// ---------------------------------------------------------------------------
// Generic NT SGEMM:  C[m,n] = sum_k A[m,k] * Bw[n,k]   (both K-contiguous)
// 128x128 block tile, BK=16, 256 threads, 8x8 per-thread tile,
// double-buffered smem (reg prefetch -> STS), 1 sync/tile.
// Assumes M % 128 == 0 and Kd % 16 == 0 (true for all call sites).
// EPI==1: C = softplus(C + bias[n])
// ---------------------------------------------------------------------------
#define STS_TILE(bufi)                                                          \
    do {                                                                        \
        As[bufi][lc + 0][lr] = ra0.x; As[bufi][lc + 1][lr] = ra0.y;             \
        As[bufi][lc + 2][lr] = ra0.z; As[bufi][lc + 3][lr] = ra0.w;             \
        As[bufi][lc + 4][lr] = ra1.x; As[bufi][lc + 5][lr] = ra1.y;             \
        As[bufi][lc + 6][lr] = ra1.z; As[bufi][lc + 7][lr] = ra1.w;             \
        Bs[bufi][lc + 0][lr] = rb0.x; Bs[bufi][lc + 1][lr] = rb0.y;             \
        Bs[bufi][lc + 2][lr] = rb0.z; Bs[bufi][lc + 3][lr] = rb0.w;             \
        Bs[bufi][lc + 4][lr] = rb1.x; Bs[bufi][lc + 5][lr] = rb1.y;             \
        Bs[bufi][lc + 6][lr] = rb1.z; Bs[bufi][lc + 7][lr] = rb1.w;             \
    } while (0)

template <int EPI>
__global__ void __launch_bounds__(256, 2)
sgemm_nt(const float* __restrict__ A, int lda,
         const float* __restrict__ Bw, int ldb,
         float* __restrict__ C, int ldc,
         int Nc, int Kd, const float* __restrict__ bias)
{
    __shared__ float As[2][16][128];
    __shared__ float Bs[2][16][128];

    const int t  = threadIdx.x;
    const int tx = t & 15;
    const int ty = t >> 4;
    const int m0 = blockIdx.y * 128;
    const int n0 = blockIdx.x * 128;

    // loader mapping: 2 threads per row, 8 floats (2x float4) each
    const int lr = t >> 1;          // 0..127: tile row
    const int lc = (t & 1) * 8;     // 0 or 8: k offset

    const float* Ap = A + (size_t)(m0 + lr) * lda + lc;
    const float* Bp = Bw + (size_t)(n0 + lr) * ldb + lc;
    const bool bval = (n0 + lr) < Nc;
    const float4 fz = make_float4(0.f, 0.f, 0.f, 0.f);

    float4 ra0, ra1, rb0, rb1;

    // prologue: tile 0 -> buffer 0
    ra0 = *(const float4*)(Ap + 0);
    ra1 = *(const float4*)(Ap + 4);
    rb0 = bval ? *(const float4*)(Bp + 0) : fz;
    rb1 = bval ? *(const float4*)(Bp + 4) : fz;
    STS_TILE(0);
    __syncthreads();

    float acc[8][8];
#pragma unroll
    for (int i = 0; i < 8; i++)
#pragma unroll
        for (int j = 0; j < 8; j++) acc[i][j] = 0.f;

    const int ntiles = Kd >> 4;
    int buf = 0;
    for (int tgt = 0; tgt < ntiles; tgt++) {
        if (tgt + 1 < ntiles) {
            const int k0 = (tgt + 1) << 4;
            ra0 = *(const float4*)(Ap + k0);
            ra1 = *(const float4*)(Ap + k0 + 4);
            rb0 = bval ? *(const float4*)(Bp + k0) : fz;
            rb1 = bval ? *(const float4*)(Bp + k0 + 4) : fz;
        }
#pragma unroll
        for (int k = 0; k < 16; k++) {
            float av[8], bv[8];
            *(float4*)&av[0] = *(const float4*)&As[buf][k][ty * 8];
            *(float4*)&av[4] = *(const float4*)&As[buf][k][ty * 8 + 4];
            *(float4*)&bv[0] = *(const float4*)&Bs[buf][k][tx * 8];
            *(float4*)&bv[4] = *(const float4*)&Bs[buf][k][tx * 8 + 4];
#pragma unroll
            for (int i = 0; i < 8; i++)
#pragma unroll
                for (int j = 0; j < 8; j++)
                    acc[i][j] = fmaf(av[i], bv[j], acc[i][j]);
        }
        if (tgt + 1 < ntiles) {
            const int nb = buf ^ 1;
            STS_TILE(nb);
        }
        __syncthreads();
        buf ^= 1;
    }

#pragma unroll
    for (int i = 0; i < 8; i++) {
        const size_t m = (size_t)(m0 + ty * 8 + i);
#pragma unroll
        for (int j = 0; j < 8; j++) {
            const int nn = n0 + tx * 8 + j;
            if (nn < Nc) {
                float c = acc[i][j];
                if (EPI == 1) c = softplusf(c + bias[nn]);
                C[m * ldc + nn] = c;
            }
        }
    }
}

// ---------------------------------------------------------------------------
// Depthwise causal conv1d (K=4, left pad 3) + bias + silu.
// Reads u-half of g_proj ([BL, 8192], cols 0..D), writes g_u ([BL, D]).
// ---------------------------------------------------------------------------
__global__ void conv_silu_kernel(const float* __restrict__ proj,
                                 const float* __restrict__ cw,
                                 const float* __restrict__ cb,
                                 float* __restrict__ u)
{
    const int idx = blockIdx.x * blockDim.x + threadIdx.x;
    if (idx >= BL * DDIM) return;
    const int d  = idx & (DDIM - 1);
    const int bl = idx >> 12;          // idx / DDIM
    const int l  = bl & (LSEQ - 1);

    const float4 w = *(const float4*)(cw + d * 4);   // conv_w[d,0,0..3]
    const float* base = proj + (size_t)bl * P2D + d;
    float acc = cb[d];
    if (l >= 3) acc = fmaf(w.x, base[-3 * P2D], acc);
    if (l >= 2) acc = fmaf(w.y, base[-2 * P2D], acc);
    if (l >= 1) acc = fmaf(w.z, base[-1 * P2D], acc);
    acc = fmaf(w.w, base[0], acc);
    u[idx] = siluf(acc);
}

// ---------------------------------------------------------------------------
// Selective scan. One thread per (b, d, n): state in a register, L sequential.
// Block = 256 threads = 16 d-sequences x 16 states. 16-lane shfl reduction
// produces y[b,l,d]; fused epilogue: y_final = (y + u*Dp) * silu(gate).
// ---------------------------------------------------------------------------
__global__ void __launch_bounds__(256)
scan_kernel(const float* __restrict__ dtg,   // [BL, D]
            const float* __restrict__ ug,    // [BL, D]
            const float* __restrict__ spg,   // [BL, 160] (B at 128, C at 144)
            const float* __restrict__ Alog,  // [D, 16]
            const float* __restrict__ Dp,    // [D]
            const float* __restrict__ proj,  // [BL, 8192] (gate at col D+d)
            float* __restrict__ yg)          // [BL, D]
{
    const int b   = blockIdx.y;
    const int d0  = blockIdx.x * 16;
    const int t   = threadIdx.x;
    const int seq = t >> 4;
    const int n   = t & 15;
    const int d   = d0 + seq;

    __shared__ float sdt[64][16];
    __shared__ float su [64][16];
    __shared__ float sB [64][16];
    __shared__ float sC [64][16];
    __shared__ float sy [64][16];

    const float a = -__expf(Alog[d * NSTATE + n]);
    float s = 0.f;

    const int i16 = t >> 4, j16 = t & 15;
    const int i32 = t >> 5, j32 = t & 31;

    for (int l0 = 0; l0 < LSEQ; l0 += 64) {
        const int bl0 = b * LSEQ + l0;
        // stage dt / u tiles (coalesced 64B rows)
#pragma unroll
        for (int r = 0; r < 4; r++) {
            const int ii = i16 + r * 16;
            sdt[ii][j16] = dtg[(size_t)(bl0 + ii) * DDIM + d0 + j16];
            su [ii][j16] = ug [(size_t)(bl0 + ii) * DDIM + d0 + j16];
        }
        // stage B/C tiles (32 contiguous floats per row, sp cols 128..159)
#pragma unroll
        for (int r = 0; r < 8; r++) {
            const int ii = i32 + r * 8;
            const float v = spg[(size_t)(bl0 + ii) * SP_W + RRANK + j32];
            if (j32 < 16) sB[ii][j32] = v;
            else          sC[ii][j32 - 16] = v;
        }
        __syncthreads();

#pragma unroll 4
        for (int il = 0; il < 64; il++) {
            const float dtv = sdt[il][seq];
            const float dA  = __expf(a * dtv);
            const float dBu = dtv * sB[il][n] * su[il][seq];
            s = fmaf(dA, s, dBu);
            float p = s * sC[il][n];
            p += __shfl_xor_sync(0xffffffffu, p, 8);
            p += __shfl_xor_sync(0xffffffffu, p, 4);
            p += __shfl_xor_sync(0xffffffffu, p, 2);
            p += __shfl_xor_sync(0xffffffffu, p, 1);
            if (n == 0) sy[il][seq] = p;
        }
        __syncthreads();

        // fused epilogue
#pragma unroll
        for (int r = 0; r < 4; r++) {
            const int ii = i16 + r * 16;
            const float yy = sy[ii][j16];
            const float uu = su[ii][j16];
            const float g  = proj[(size_t)(bl0 + ii) * P2D + DDIM + d0 + j16];
            const float yf = fmaf(uu, Dp[d0 + j16], yy);
            yg[(size_t)(bl0 + ii) * DDIM + d0 + j16] = yf * siluf(g);
        }
        __syncthreads();   // protect smem reuse next chunk
    }
}

// ---------------------------------------------------------------------------
// Launch sequence (graph-capturable: kernel launches only)
// ---------------------------------------------------------------------------
extern "C" void kernel_launch(void* const* d_in, const int* in_sizes, int n_in,
                              void* d_out, int out_size)
{
    const float* hs   = (const float*)d_in[0];  // [B,L,H]
    const float* w_in = (const float*)d_in[1];  // [2D,H]
    const float* cw   = (const float*)d_in[2];  // [D,1,K]
    const float* cb   = (const float*)d_in[3];  // [D]
    const float* w_x  = (const float*)d_in[4];  // [160,D]
    const float* w_dt = (const float*)d_in[5];  // [D,R]
    const float* b_dt = (const float*)d_in[6];  // [D]
    const float* alog = (const float*)d_in[7];  // [D,N]
    const float* dpar = (const float*)d_in[8];  // [D]
    const float* w_o  = (const float*)d_in[9];  // [H,D]
    float* out = (float*)d_out;                 // [B,L,H]

    float *proj, *u, *sp, *dtb, *y;
    cudaGetSymbolAddress((void**)&proj, g_proj);
    cudaGetSymbolAddress((void**)&u,    g_u);
    cudaGetSymbolAddress((void**)&sp,   g_sp);
    cudaGetSymbolAddress((void**)&dtb,  g_dt);
    cudaGetSymbolAddress((void**)&y,    g_y);

    const dim3 blk(256);

    // 1) in_proj: proj[BL, 8192] = hs[BL, 2048] @ w_in^T
    sgemm_nt<0><<<dim3(P2D / 128, BL / 128), blk>>>(
        hs, HDIM, w_in, HDIM, proj, P2D, P2D, HDIM, nullptr);

    // 2) depthwise causal conv + silu -> u[BL, D]
    conv_silu_kernel<<<(BL * DDIM) / 256, 256>>>(proj, cw, cb, u);

    // 3) x_proj: sp[BL, 160] = u @ w_x^T
    sgemm_nt<0><<<dim3(2, BL / 128), blk>>>(
        u, DDIM, w_x, DDIM, sp, SP_W, SP_W, DDIM, nullptr);

    // 4) dt_proj + bias + softplus: dt[BL, D] = softplus(ts @ w_dt^T + b_dt)
    sgemm_nt<1><<<dim3(DDIM / 128, BL / 128), blk>>>(
        sp, SP_W, w_dt, RRANK, dtb, DDIM, DDIM, RRANK, b_dt);

    // 5) selective scan + D-skip + gate (fused)
    scan_kernel<<<dim3(DDIM / 16, BSZ), 256>>>(dtb, u, sp, alog, dpar, proj, y);

    // 6) out_proj: out[BL, H] = y @ w_o^T
    sgemm_nt<0><<<dim3(HDIM / 128, BL / 128), blk>>>(
        y, DDIM, w_o, DDIM, out, HDIM, HDIM, DDIM, nullptr);
}

// round 3
// speedup vs baseline: 2.7174x; 2.7174x over previous
#include <cuda_runtime.h>
#include <cuda_bf16.h>
#include <math.h>
#include <stdint.h>

// Problem constants (fixed by setup_inputs)
#define BSZ    2
#define LSEQ   1024
#define HDIM   2048
#define DDIM   4096
#define NSTATE 16
#define RRANK  128
#define KCONV  4
#define BL     (BSZ * LSEQ)          // 2048 rows
#define P2D    (2 * DDIM)            // 8192
#define SP_W   (RRANK + 2 * NSTATE)  // 160

// ---------------------------------------------------------------------------
// Scratch: static device globals (no cudaMalloc allowed)
// ---------------------------------------------------------------------------
__device__ float g_proj[(size_t)BL * P2D];     // in_proj output [BL, 8192] (u | gate)
__device__ float g_sp  [(size_t)BL * SP_W];    // x_proj output [BL, 160]
__device__ float g_dt  [(size_t)BL * DDIM];    // softplus(dt_proj) [BL, D]

// bf16 hi/lo split buffers
__device__ __nv_bfloat16 g_hs_h[(size_t)BL * HDIM],  g_hs_l[(size_t)BL * HDIM];
__device__ __nv_bfloat16 g_win_h[(size_t)P2D * HDIM], g_win_l[(size_t)P2D * HDIM];
__device__ __nv_bfloat16 g_u_h[(size_t)BL * DDIM],   g_u_l[(size_t)BL * DDIM];
__device__ __nv_bfloat16 g_wx_h[(size_t)SP_W * DDIM], g_wx_l[(size_t)SP_W * DDIM];
__device__ __nv_bfloat16 g_sp_h[(size_t)BL * SP_W],  g_sp_l[(size_t)BL * SP_W];
__device__ __nv_bfloat16 g_wdt_h[(size_t)DDIM * RRANK], g_wdt_l[(size_t)DDIM * RRANK];
__device__ __nv_bfloat16 g_y_h[(size_t)BL * DDIM],   g_y_l[(size_t)BL * DDIM];
__device__ __nv_bfloat16 g_wo_h[(size_t)HDIM * DDIM], g_wo_l[(size_t)HDIM * DDIM];

__device__ __forceinline__ float softplusf(float x) {
    return (x > 20.f) ? x : log1pf(__expf(x));
}
__device__ __forceinline__ float siluf(float x) {
    return x / (1.f + __expf(-x));
}

// ---------------------------------------------------------------------------
// PTX helpers (sm_80+ portable: cp.async / ldmatrix / mma.sync)
// ---------------------------------------------------------------------------
__device__ __forceinline__ uint32_t smem_u32(const void* p) {
    uint32_t a;
    asm("{ .reg .u64 t; cvta.to.shared.u64 t, %1; cvt.u32.u64 %0, t; }" : "=r"(a) : "l"(p));
    return a;
}
__device__ __forceinline__ void cpa16(uint32_t dst, const void* src, int sz) {
    asm volatile("cp.async.cg.shared.global [%0], [%1], 16, %2;"
                 :: "r"(dst), "l"(src), "r"(sz) : "memory");
}
__device__ __forceinline__ void cpa_commit() {
    asm volatile("cp.async.commit_group;" ::: "memory");
}
template <int N>
__device__ __forceinline__ void cpa_wait() {
    asm volatile("cp.async.wait_group %0;" :: "n"(N) : "memory");
}
__device__ __forceinline__ void ldsm_x4(uint32_t* r, uint32_t addr) {
    asm volatile("ldmatrix.sync.aligned.m8n8.x4.shared.b16 {%0,%1,%2,%3}, [%4];"
                 : "=r"(r[0]), "=r"(r[1]), "=r"(r[2]), "=r"(r[3]) : "r"(addr));
}
__device__ __forceinline__ void ldsm_x2(uint32_t* r, uint32_t addr) {
    asm volatile("ldmatrix.sync.aligned.m8n8.x2.shared.b16 {%0,%1}, [%2];"
                 : "=r"(r[0]), "=r"(r[1]) : "r"(addr));
}
__device__ __forceinline__ void mma_bf16(float* c, const uint32_t* a, const uint32_t* b) {
    asm volatile(
        "mma.sync.aligned.m16n8k16.row.col.f32.bf16.bf16.f32 "
        "{%0,%1,%2,%3}, {%4,%5,%6,%7}, {%8,%9}, {%0,%1,%2,%3};"
        : "+f"(c[0]), "+f"(c[1]), "+f"(c[2]), "+f"(c[3])
        : "r"(a[0]), "r"(a[1]), "r"(a[2]), "r"(a[3]), "r"(b[0]), "r"(b[1]));
}

// ---------------------------------------------------------------------------
// fp32 -> bf16 hi/lo split (vectorized by 4)
// ---------------------------------------------------------------------------
__global__ void cvt_hilo4(const float* __restrict__ x,
                          __nv_bfloat16* __restrict__ h,
                          __nv_bfloat16* __restrict__ l, int n4)
{
    int i = blockIdx.x * blockDim.x + threadIdx.x;
    if (i >= n4) return;
    float4 v = ((const float4*)x)[i];
    __nv_bfloat162 h0 = __floats2bfloat162_rn(v.x, v.y);
    __nv_bfloat162 h1 = __floats2bfloat162_rn(v.z, v.w);
    __nv_bfloat162 l0 = __floats2bfloat162_rn(v.x - __low2float(h0), v.y - __high2float(h0));
    __nv_bfloat162 l1 = __floats2bfloat162_rn(v.z - __low2float(h1), v.w - __high2float(h1));
    ((__nv_bfloat162*)h)[2 * i]     = h0;
    ((__nv_bfloat162*)h)[2 * i + 1] = h1;
    ((__nv_bfloat162*)l)[2 * i]     = l0;
    ((__nv_bfloat162*)l)[2 * i + 1] = l1;
}

// ---------------------------------------------------------------------------
// Tensor-core split-bf16 GEMM:  C[m,n] = sum_k A[m,k]*Bw[n,k]
//   A ~ Ah+Al, Bw ~ Bh+Bl (bf16);  C = Ah*Bh + Ah*Bl + Al*Bh (fp32 acc)
// 128x128 CTA tile, BK=64, 8 warps (2x4), double-buffered cp.async stages.
// Smem tile layout: 128 rows x 128B (64 bf16) with SW128 XOR swizzle.
// EPI==1: C = softplus(C + bias[n])
// ---------------------------------------------------------------------------
#define TILE_BYTES  16384
#define STAGE_BYTES (4 * TILE_BYTES)     // Ah | Al | Bh | Bl
#define DYN_SMEM    (2 * STAGE_BYTES)

__device__ __forceinline__ void load_tile_async(
    const __nv_bfloat16* __restrict__ src, int ld, int row0, int k0,
    uint32_t dstbase, int tid, int nrows)
{
#pragma unroll
    for (int i = 0; i < 4; i++) {
        int u   = tid + i * 256;
        int row = u >> 3;
        int sub = u & 7;
        uint32_t off = (uint32_t)(row * 128 + sub * 16);
        off ^= ((off >> 3) & 0x70u);                  // SW128 swizzle
        const int  ok = (row0 + row) < nrows;
        const void* s = src + (size_t)(row0 + (ok ? row : 0)) * ld + k0 + sub * 8;
        cpa16(dstbase + off, s, ok ? 16 : 0);
    }
}

template <int EPI>
__global__ void __launch_bounds__(256, 1)
tgemm(const __nv_bfloat16* __restrict__ Ah, const __nv_bfloat16* __restrict__ Al, int lda,
      const __nv_bfloat16* __restrict__ Bh, const __nv_bfloat16* __restrict__ Bl, int ldb,
      float* __restrict__ C, int ldc, int Nc, int Kd, const float* __restrict__ bias)
{
    extern __shared__ __align__(1024) char smem[];
    const uint32_t sbase = smem_u32(smem);

    const int tid  = threadIdx.x;
    const int wid  = tid >> 5;
    const int lane = tid & 31;
    const int m0   = blockIdx.y * 128;
    const int n0   = blockIdx.x * 128;
    const int wm   = wid >> 2;           // 0..1 -> 64-row slab
    const int wn   = wid & 3;            // 0..3 -> 32-col slab

    // ldmatrix per-lane address components
    const uint32_t kxor  = (uint32_t)((lane & 7) << 4);
    const uint32_t khiA  = (uint32_t)((lane >> 4) * 16);         // A: x4 col-8 select
    const uint32_t khiB  = (uint32_t)(((lane >> 3) & 1) * 16);   // B: x2 matrix select
    uint32_t rowA[4], rowB[4];
#pragma unroll
    for (int i = 0; i < 4; i++)
        rowA[i] = (uint32_t)((wm * 64 + i * 16 + (lane & 15)) * 128);
#pragma unroll
    for (int j = 0; j < 4; j++)
        rowB[j] = (uint32_t)((wn * 32 + j * 8 + (lane & 7)) * 128);

    float acc[4][4][4];
#pragma unroll
    for (int i = 0; i < 4; i++)
#pragma unroll
        for (int j = 0; j < 4; j++)
#pragma unroll
            for (int r = 0; r < 4; r++) acc[i][j][r] = 0.f;

    const int nch = Kd >> 6;

    // prologue: stage 0 -> buffer 0
    {
        uint32_t st = sbase;
        load_tile_async(Ah, lda, m0, 0, st,                  tid, 1 << 30);
        load_tile_async(Al, lda, m0, 0, st + TILE_BYTES,     tid, 1 << 30);
        load_tile_async(Bh, ldb, n0, 0, st + 2 * TILE_BYTES, tid, Nc);
        load_tile_async(Bl, ldb, n0, 0, st + 3 * TILE_BYTES, tid, Nc);
        cpa_commit();
    }

    for (int c = 0; c < nch; c++) {
        if (c + 1 < nch) {
            uint32_t st = sbase + ((c + 1) & 1) * STAGE_BYTES;
            const int k0 = (c + 1) << 6;
            load_tile_async(Ah, lda, m0, k0, st,                  tid, 1 << 30);
            load_tile_async(Al, lda, m0, k0, st + TILE_BYTES,     tid, 1 << 30);
            load_tile_async(Bh, ldb, n0, k0, st + 2 * TILE_BYTES, tid, Nc);
            load_tile_async(Bl, ldb, n0, k0, st + 3 * TILE_BYTES, tid, Nc);
            cpa_commit();
            cpa_wait<1>();
        } else {
            cpa_wait<0>();
        }
        __syncthreads();

        const uint32_t aH = sbase + (c & 1) * STAGE_BYTES;
        const uint32_t aL = aH + TILE_BYTES;
        const uint32_t bH = aH + 2 * TILE_BYTES;
        const uint32_t bL = aH + 3 * TILE_BYTES;

#pragma unroll
        for (int ks = 0; ks < 4; ks++) {
            const uint32_t kpA = (uint32_t)(ks * 32 + khiA) ^ kxor;
            const uint32_t kpB = (uint32_t)(ks * 32 + khiB) ^ kxor;
            uint32_t ah[4][4], al[4][4];
#pragma unroll
            for (int i = 0; i < 4; i++) {
                ldsm_x4(ah[i], aH + rowA[i] + kpA);
                ldsm_x4(al[i], aL + rowA[i] + kpA);
            }
#pragma unroll
            for (int j = 0; j < 4; j++) {
                uint32_t bh[2], bl[2];
                ldsm_x2(bh, bH + rowB[j] + kpB);
                ldsm_x2(bl, bL + rowB[j] + kpB);
#pragma unroll
                for (int i = 0; i < 4; i++) {
                    mma_bf16(acc[i][j], ah[i], bh);
                    mma_bf16(acc[i][j], ah[i], bl);
                    mma_bf16(acc[i][j], al[i], bh);
                }
            }
        }
        __syncthreads();
    }

    // epilogue: direct global stores (float2 per half-fragment)
    const int qr = lane >> 2;
    const int qc = (lane & 3) * 2;
#pragma unroll
    for (int i = 0; i < 4; i++) {
        const int r0 = m0 + wm * 64 + i * 16 + qr;
#pragma unroll
        for (int j = 0; j < 4; j++) {
            const int nn = n0 + wn * 32 + j * 8 + qc;
            if (nn < Nc) {
                float2 v0 = make_float2(acc[i][j][0], acc[i][j][1]);
                float2 v1 = make_float2(acc[i][j][2], acc[i][j][3]);
                if (EPI == 1) {
                    const float b0 = bias[nn], b1 = bias[nn + 1];
                    v0.x = softplusf(v0.x + b0); v0.y = softplusf(v0.y + b1);
                    v1.x = softplusf(v1.x + b0); v1.y = softplusf(v1.y + b1);
                }
                *(float2*)(C + (size_t)r0 * ldc + nn)       = v0;
                *(float2*)(C + (size_t)(r0 + 8) * ldc + nn) = v1;
            }
        }
    }
}

// ---------------------------------------------------------------------------
// Depthwise causal conv1d (K=4) + bias + silu -> bf16 hi/lo
// ---------------------------------------------------------------------------
__global__ void conv_silu_kernel(const float* __restrict__ proj,
                                 const float* __restrict__ cw,
                                 const float* __restrict__ cb,
                                 __nv_bfloat16* __restrict__ uh,
                                 __nv_bfloat16* __restrict__ ul)
{
    const int idx = blockIdx.x * blockDim.x + threadIdx.x;
    if (idx >= BL * DDIM) return;
    const int d  = idx & (DDIM - 1);
    const int bl = idx >> 12;
    const int l  = bl & (LSEQ - 1);

    const float4 w = *(const float4*)(cw + d * 4);
    const float* base = proj + (size_t)bl * P2D + d;
    float acc = cb[d];
    if (l >= 3) acc = fmaf(w.x, base[-3 * P2D], acc);
    if (l >= 2) acc = fmaf(w.y, base[-2 * P2D], acc);
    if (l >= 1) acc = fmaf(w.z, base[-1 * P2D], acc);
    acc = fmaf(w.w, base[0], acc);
    const float v = siluf(acc);
    const __nv_bfloat16 h = __float2bfloat16(v);
    uh[idx] = h;
    ul[idx] = __float2bfloat16(v - __bfloat162float(h));
}

// ---------------------------------------------------------------------------
// Selective scan (state-in-register, shfl reduction, fused gate epilogue)
// ---------------------------------------------------------------------------
__global__ void __launch_bounds__(256)
scan_kernel(const float* __restrict__ dtg,          // [BL, D]
            const __nv_bfloat16* __restrict__ uhg,  // [BL, D]
            const __nv_bfloat16* __restrict__ ulg,  // [BL, D]
            const float* __restrict__ spg,          // [BL, 160]
            const float* __restrict__ Alog,         // [D, 16]
            const float* __restrict__ Dp,           // [D]
            const float* __restrict__ proj,         // [BL, 8192] gate at D+d
            __nv_bfloat16* __restrict__ yh,
            __nv_bfloat16* __restrict__ yl)
{
    const int b   = blockIdx.y;
    const int d0  = blockIdx.x * 16;
    const int t   = threadIdx.x;
    const int seq = t >> 4;
    const int n   = t & 15;
    const int d   = d0 + seq;

    __shared__ float sdt[64][16];
    __shared__ float su [64][16];
    __shared__ float sB [64][16];
    __shared__ float sC [64][16];
    __shared__ float sy [64][16];

    const float a = -__expf(Alog[d * NSTATE + n]);
    float s = 0.f;

    const int i16 = t >> 4, j16 = t & 15;
    const int i32 = t >> 5, j32 = t & 31;

    for (int l0 = 0; l0 < LSEQ; l0 += 64) {
        const int bl0 = b * LSEQ + l0;
#pragma unroll
        for (int r = 0; r < 4; r++) {
            const int ii = i16 + r * 16;
            const size_t off = (size_t)(bl0 + ii) * DDIM + d0 + j16;
            sdt[ii][j16] = dtg[off];
            su [ii][j16] = __bfloat162float(uhg[off]) + __bfloat162float(ulg[off]);
        }
#pragma unroll
        for (int r = 0; r < 8; r++) {
            const int ii = i32 + r * 8;
            const float v = spg[(size_t)(bl0 + ii) * SP_W + RRANK + j32];
            if (j32 < 16) sB[ii][j32] = v;
            else          sC[ii][j32 - 16] = v;
        }
        __syncthreads();

#pragma unroll 4
        for (int il = 0; il < 64; il++) {
            const float dtv = sdt[il][seq];
            const float dA  = __expf(a * dtv);
            const float dBu = dtv * sB[il][n] * su[il][seq];
            s = fmaf(dA, s, dBu);
            float p = s * sC[il][n];
            p += __shfl_xor_sync(0xffffffffu, p, 8);
            p += __shfl_xor_sync(0xffffffffu, p, 4);
            p += __shfl_xor_sync(0xffffffffu, p, 2);
            p += __shfl_xor_sync(0xffffffffu, p, 1);
            if (n == 0) sy[il][seq] = p;
        }
        __syncthreads();

#pragma unroll
        for (int r = 0; r < 4; r++) {
            const int ii = i16 + r * 16;
            const float yy = sy[ii][j16];
            const float uu = su[ii][j16];
            const float g  = proj[(size_t)(bl0 + ii) * P2D + DDIM + d0 + j16];
            const float yf = fmaf(uu, Dp[d0 + j16], yy) * siluf(g);
            const size_t off = (size_t)(bl0 + ii) * DDIM + d0 + j16;
            const __nv_bfloat16 h = __float2bfloat16(yf);
            yh[off] = h;
            yl[off] = __float2bfloat16(yf - __bfloat162float(h));
        }
        __syncthreads();
    }
}

// ---------------------------------------------------------------------------
// Launch sequence (graph-capturable: kernel launches only)
// ---------------------------------------------------------------------------
extern "C" void kernel_launch(void* const* d_in, const int* in_sizes, int n_in,
                              void* d_out, int out_size)
{
    const float* hs   = (const float*)d_in[0];  // [B,L,H]
    const float* w_in = (const float*)d_in[1];  // [2D,H]
    const float* cw   = (const float*)d_in[2];  // [D,1,K]
    const float* cb   = (const float*)d_in[3];  // [D]
    const float* w_x  = (const float*)d_in[4];  // [160,D]
    const float* w_dt = (const float*)d_in[5];  // [D,R]
    const float* b_dt = (const float*)d_in[6];  // [D]
    const float* alog = (const float*)d_in[7];  // [D,N]
    const float* dpar = (const float*)d_in[8];  // [D]
    const float* w_o  = (const float*)d_in[9];  // [H,D]
    float* out = (float*)d_out;                 // [B,L,H]

    float *proj, *sp, *dtb;
    __nv_bfloat16 *hs_h, *hs_l, *win_h, *win_l, *u_h, *u_l, *wx_h, *wx_l;
    __nv_bfloat16 *sp_h, *sp_l, *wdt_h, *wdt_l, *y_h, *y_l, *wo_h, *wo_l;
    cudaGetSymbolAddress((void**)&proj,  g_proj);
    cudaGetSymbolAddress((void**)&sp,    g_sp);
    cudaGetSymbolAddress((void**)&dtb,   g_dt);
    cudaGetSymbolAddress((void**)&hs_h,  g_hs_h);  cudaGetSymbolAddress((void**)&hs_l,  g_hs_l);
    cudaGetSymbolAddress((void**)&win_h, g_win_h); cudaGetSymbolAddress((void**)&win_l, g_win_l);
    cudaGetSymbolAddress((void**)&u_h,   g_u_h);   cudaGetSymbolAddress((void**)&u_l,   g_u_l);
    cudaGetSymbolAddress((void**)&wx_h,  g_wx_h);  cudaGetSymbolAddress((void**)&wx_l,  g_wx_l);
    cudaGetSymbolAddress((void**)&sp_h,  g_sp_h);  cudaGetSymbolAddress((void**)&sp_l,  g_sp_l);
    cudaGetSymbolAddress((void**)&wdt_h, g_wdt_h); cudaGetSymbolAddress((void**)&wdt_l, g_wdt_l);
    cudaGetSymbolAddress((void**)&y_h,   g_y_h);   cudaGetSymbolAddress((void**)&y_l,   g_y_l);
    cudaGetSymbolAddress((void**)&wo_h,  g_wo_h);  cudaGetSymbolAddress((void**)&wo_l,  g_wo_l);

    cudaFuncSetAttribute(tgemm<0>, cudaFuncAttributeMaxDynamicSharedMemorySize, DYN_SMEM);
    cudaFuncSetAttribute(tgemm<1>, cudaFuncAttributeMaxDynamicSharedMemorySize, DYN_SMEM);

    // 0) fp32 -> bf16 hi/lo conversions
    {
        int n;
        n = BL * HDIM / 4;     cvt_hilo4<<<(n + 255) / 256, 256>>>(hs,   hs_h,  hs_l,  n);
        n = P2D * HDIM / 4;    cvt_hilo4<<<(n + 255) / 256, 256>>>(w_in, win_h, win_l, n);
        n = SP_W * DDIM / 4;   cvt_hilo4<<<(n + 255) / 256, 256>>>(w_x,  wx_h,  wx_l,  n);
        n = DDIM * RRANK / 4;  cvt_hilo4<<<(n + 255) / 256, 256>>>(w_dt, wdt_h, wdt_l, n);
        n = HDIM * DDIM / 4;   cvt_hilo4<<<(n + 255) / 256, 256>>>(w_o,  wo_h,  wo_l,  n);
    }

    // 1) in_proj: proj[2048, 8192] = hs @ w_in^T
    tgemm<0><<<dim3(P2D / 128, BL / 128), 256, DYN_SMEM>>>(
        hs_h, hs_l, HDIM, win_h, win_l, HDIM, proj, P2D, P2D, HDIM, nullptr);

    // 2) conv + silu -> u (hi/lo)
    conv_silu_kernel<<<(BL * DDIM) / 256, 256>>>(proj, cw, cb, u_h, u_l);

    // 3) x_proj: sp[2048, 160] = u @ w_x^T
    tgemm<0><<<dim3(2, BL / 128), 256, DYN_SMEM>>>(
        u_h, u_l, DDIM, wx_h, wx_l, DDIM, sp, SP_W, SP_W, DDIM, nullptr);

    // 3b) split sp for dt_proj
    {
        int n = BL * SP_W / 4;
        cvt_hilo4<<<(n + 255) / 256, 256>>>(sp, sp_h, sp_l, n);
    }

    // 4) dt_proj + bias + softplus: dt[2048, 4096]
    tgemm<1><<<dim3(DDIM / 128, BL / 128), 256, DYN_SMEM>>>(
        sp_h, sp_l, SP_W, wdt_h, wdt_l, RRANK, dtb, DDIM, DDIM, RRANK, b_dt);

    // 5) selective scan + D-skip + gate (fused) -> y (hi/lo)
    scan_kernel<<<dim3(DDIM / 16, BSZ), 256>>>(dtb, u_h, u_l, sp, alog, dpar, proj, y_h, y_l);

    // 6) out_proj: out[2048, 2048] = y @ w_o^T
    tgemm<0><<<dim3(HDIM / 128, BL / 128), 256, DYN_SMEM>>>(
        y_h, y_l, DDIM, wo_h, wo_l, DDIM, out, HDIM, HDIM, DDIM, nullptr);
}

// round 4
// speedup vs baseline: 2.9273x; 1.0772x over previous
#include <cuda_runtime.h>
#include <cuda_bf16.h>
#include <math.h>
#include <stdint.h>

// Problem constants (fixed by setup_inputs)
#define BSZ    2
#define LSEQ   1024
#define HDIM   2048
#define DDIM   4096
#define NSTATE 16
#define RRANK  128
#define KCONV  4
#define BL     (BSZ * LSEQ)          // 2048 rows
#define P2D    (2 * DDIM)            // 8192
#define SP_W   (RRANK + 2 * NSTATE)  // 160
#define XP_SPLIT 8                   // split-K factor for x_proj
#define XP_KLEN  (DDIM / XP_SPLIT)   // 512

// ---------------------------------------------------------------------------
// Scratch: static device globals (no cudaMalloc allowed)
// ---------------------------------------------------------------------------
__device__ float g_proj[(size_t)BL * P2D];     // in_proj output [BL, 8192] (u | gate)
__device__ float g_sp  [(size_t)BL * SP_W];    // x_proj output [BL, 160]
__device__ float g_dt  [(size_t)BL * DDIM];    // softplus(dt_proj) [BL, D]
__device__ float g_xpp [(size_t)XP_SPLIT * BL * SP_W];  // split-K partials

// bf16 hi/lo split buffers
__device__ __nv_bfloat16 g_hs_h[(size_t)BL * HDIM],  g_hs_l[(size_t)BL * HDIM];
__device__ __nv_bfloat16 g_win_h[(size_t)P2D * HDIM], g_win_l[(size_t)P2D * HDIM];
__device__ __nv_bfloat16 g_u_h[(size_t)BL * DDIM],   g_u_l[(size_t)BL * DDIM];
__device__ __nv_bfloat16 g_wx_h[(size_t)SP_W * DDIM], g_wx_l[(size_t)SP_W * DDIM];
__device__ __nv_bfloat16 g_sp_h[(size_t)BL * SP_W],  g_sp_l[(size_t)BL * SP_W];
__device__ __nv_bfloat16 g_wdt_h[(size_t)DDIM * RRANK], g_wdt_l[(size_t)DDIM * RRANK];
__device__ __nv_bfloat16 g_y_h[(size_t)BL * DDIM],   g_y_l[(size_t)BL * DDIM];
__device__ __nv_bfloat16 g_wo_h[(size_t)HDIM * DDIM], g_wo_l[(size_t)HDIM * DDIM];

__device__ __forceinline__ float softplusf(float x) {
    return (x > 20.f) ? x : log1pf(__expf(x));
}
__device__ __forceinline__ float siluf(float x) {
    return x / (1.f + __expf(-x));
}

// ---------------------------------------------------------------------------
// PTX helpers (sm_80+ portable: cp.async / ldmatrix / mma.sync)
// ---------------------------------------------------------------------------
__device__ __forceinline__ uint32_t smem_u32(const void* p) {
    uint32_t a;
    asm("{ .reg .u64 t; cvta.to.shared.u64 t, %1; cvt.u32.u64 %0, t; }" : "=r"(a) : "l"(p));
    return a;
}
__device__ __forceinline__ void cpa16(uint32_t dst, const void* src, int sz) {
    asm volatile("cp.async.cg.shared.global [%0], [%1], 16, %2;"
                 :: "r"(dst), "l"(src), "r"(sz) : "memory");
}
__device__ __forceinline__ void cpa_commit() {
    asm volatile("cp.async.commit_group;" ::: "memory");
}
template <int N>
__device__ __forceinline__ void cpa_wait() {
    asm volatile("cp.async.wait_group %0;" :: "n"(N) : "memory");
}
__device__ __forceinline__ void ldsm_x4(uint32_t* r, uint32_t addr) {
    asm volatile("ldmatrix.sync.aligned.m8n8.x4.shared.b16 {%0,%1,%2,%3}, [%4];"
                 : "=r"(r[0]), "=r"(r[1]), "=r"(r[2]), "=r"(r[3]) : "r"(addr));
}
__device__ __forceinline__ void mma_bf16(float* c, const uint32_t* a, const uint32_t* b) {
    asm volatile(
        "mma.sync.aligned.m16n8k16.row.col.f32.bf16.bf16.f32 "
        "{%0,%1,%2,%3}, {%4,%5,%6,%7}, {%8,%9}, {%0,%1,%2,%3};"
        : "+f"(c[0]), "+f"(c[1]), "+f"(c[2]), "+f"(c[3])
        : "r"(a[0]), "r"(a[1]), "r"(a[2]), "r"(a[3]), "r"(b[0]), "r"(b[1]));
}

// ---------------------------------------------------------------------------
// Merged fp32 -> bf16 hi/lo split for all 5 weight/input tensors (1 launch)
// ---------------------------------------------------------------------------
#define CVT_N0 (BL * HDIM / 4)                       // hs
#define CVT_N1 (CVT_N0 + P2D * HDIM / 4)             // + w_in
#define CVT_N2 (CVT_N1 + SP_W * DDIM / 4)            // + w_x
#define CVT_N3 (CVT_N2 + DDIM * RRANK / 4)           // + w_dt
#define CVT_N4 (CVT_N3 + HDIM * DDIM / 4)            // + w_o

__device__ __forceinline__ void cvt_one(const float* __restrict__ x,
                                        __nv_bfloat16* __restrict__ h,
                                        __nv_bfloat16* __restrict__ l, int i)
{
    float4 v = ((const float4*)x)[i];
    __nv_bfloat162 h0 = __floats2bfloat162_rn(v.x, v.y);
    __nv_bfloat162 h1 = __floats2bfloat162_rn(v.z, v.w);
    __nv_bfloat162 l0 = __floats2bfloat162_rn(v.x - __low2float(h0), v.y - __high2float(h0));
    __nv_bfloat162 l1 = __floats2bfloat162_rn(v.z - __low2float(h1), v.w - __high2float(h1));
    ((__nv_bfloat162*)h)[2 * i]     = h0;
    ((__nv_bfloat162*)h)[2 * i + 1] = h1;
    ((__nv_bfloat162*)l)[2 * i]     = l0;
    ((__nv_bfloat162*)l)[2 * i + 1] = l1;
}

__global__ void cvt_all(const float* s0, __nv_bfloat16* h0, __nv_bfloat16* l0,
                        const float* s1, __nv_bfloat16* h1, __nv_bfloat16* l1,
                        const float* s2, __nv_bfloat16* h2, __nv_bfloat16* l2,
                        const float* s3, __nv_bfloat16* h3, __nv_bfloat16* l3,
                        const float* s4, __nv_bfloat16* h4, __nv_bfloat16* l4)
{
    int i = blockIdx.x * blockDim.x + threadIdx.x;
    if (i < CVT_N0)      cvt_one(s0, h0, l0, i);
    else if (i < CVT_N1) cvt_one(s1, h1, l1, i - CVT_N0);
    else if (i < CVT_N2) cvt_one(s2, h2, l2, i - CVT_N1);
    else if (i < CVT_N3) cvt_one(s3, h3, l3, i - CVT_N2);
    else if (i < CVT_N4) cvt_one(s4, h4, l4, i - CVT_N3);
}

// ---------------------------------------------------------------------------
// Tensor-core split-bf16 GEMM:  C[m,n] = sum_k A[m,k]*Bw[n,k]
//   A ~ Ah+Al, Bw ~ Bh+Bl (bf16);  C = Ah*Bh + Ah*Bl + Al*Bh (fp32 acc)
// 128x128 CTA tile, BK=64, 8 warps (2x4), 3-stage cp.async pipeline,
// one __syncthreads per chunk. blockIdx.z = K-split slice (klen, partStride).
// EPI==1: C = softplus(C + bias[n])
// ---------------------------------------------------------------------------
#define TILE_BYTES  16384
#define STAGE_BYTES (4 * TILE_BYTES)     // Ah | Al | Bh | Bl
#define NSTAGE      3
#define DYN_SMEM    (NSTAGE * STAGE_BYTES)

__device__ __forceinline__ void load_tile_async(
    const __nv_bfloat16* __restrict__ src, int ld, int row0, int k0,
    uint32_t dstbase, int tid, int nrows)
{
#pragma unroll
    for (int i = 0; i < 4; i++) {
        int u   = tid + i * 256;
        int row = u >> 3;
        int sub = u & 7;
        uint32_t off = (uint32_t)(row * 128 + sub * 16);
        off ^= ((off >> 3) & 0x70u);                  // SW128 swizzle
        const int  ok = (row0 + row) < nrows;
        const void* s = src + (size_t)(row0 + (ok ? row : 0)) * ld + k0 + sub * 8;
        cpa16(dstbase + off, s, ok ? 16 : 0);
    }
}

template <int EPI>
__global__ void __launch_bounds__(256, 1)
tgemm(const __nv_bfloat16* __restrict__ Ah, const __nv_bfloat16* __restrict__ Al, int lda,
      const __nv_bfloat16* __restrict__ Bh, const __nv_bfloat16* __restrict__ Bl, int ldb,
      float* __restrict__ C, int ldc, int Nc, int klen,
      const float* __restrict__ bias, size_t partStride)
{
    extern __shared__ __align__(1024) char smem[];
    const uint32_t sbase = smem_u32(smem);

    const int tid  = threadIdx.x;
    const int wid  = tid >> 5;
    const int lane = tid & 31;
    const int m0   = blockIdx.y * 128;
    const int n0   = blockIdx.x * 128;
    const int kb   = blockIdx.z * klen;    // K-slice base
    C += (size_t)blockIdx.z * partStride;
    const int wm   = wid >> 2;             // 0..1 -> 64-row slab
    const int wn   = wid & 3;              // 0..3 -> 32-col slab

    // ldmatrix per-lane address components
    const uint32_t kxor = (uint32_t)((lane & 7) << 4);
    const uint32_t khiA = (uint32_t)((lane >> 4) * 16);          // A: x4 k-half select
    const uint32_t khiB = (uint32_t)(((lane >> 3) & 1) * 16);    // B: k-half select
    uint32_t rowA[4], rowB4[2];
#pragma unroll
    for (int i = 0; i < 4; i++)
        rowA[i] = (uint32_t)((wm * 64 + i * 16 + (lane & 15)) * 128);
#pragma unroll
    for (int j2 = 0; j2 < 2; j2++)
        rowB4[j2] = (uint32_t)((wn * 32 + j2 * 16 + ((lane >> 4) << 3) + (lane & 7)) * 128);

    float acc[4][4][4];
#pragma unroll
    for (int i = 0; i < 4; i++)
#pragma unroll
        for (int j = 0; j < 4; j++)
#pragma unroll
            for (int r = 0; r < 4; r++) acc[i][j][r] = 0.f;

    const int nch = klen >> 6;

    // prologue: stages 0 .. NSTAGE-2
#pragma unroll
    for (int s = 0; s < NSTAGE - 1; s++) {
        if (s < nch) {
            uint32_t st = sbase + s * STAGE_BYTES;
            const int k0 = kb + (s << 6);
            load_tile_async(Ah, lda, m0, k0, st,                  tid, 1 << 30);
            load_tile_async(Al, lda, m0, k0, st + TILE_BYTES,     tid, 1 << 30);
            load_tile_async(Bh, ldb, n0, k0, st + 2 * TILE_BYTES, tid, Nc);
            load_tile_async(Bl, ldb, n0, k0, st + 3 * TILE_BYTES, tid, Nc);
        }
        cpa_commit();
    }

    for (int c = 0; c < nch; c++) {
        cpa_wait<NSTAGE - 2>();      // stage c complete (uniform: always-commit)
        __syncthreads();

        // prefetch stage c+NSTAGE-1 (writes the buffer freed by iter c-1)
        const int cp = c + NSTAGE - 1;
        if (cp < nch) {
            uint32_t st = sbase + (cp % NSTAGE) * STAGE_BYTES;
            const int k0 = kb + (cp << 6);
            load_tile_async(Ah, lda, m0, k0, st,                  tid, 1 << 30);
            load_tile_async(Al, lda, m0, k0, st + TILE_BYTES,     tid, 1 << 30);
            load_tile_async(Bh, ldb, n0, k0, st + 2 * TILE_BYTES, tid, Nc);
            load_tile_async(Bl, ldb, n0, k0, st + 3 * TILE_BYTES, tid, Nc);
        }
        cpa_commit();

        const uint32_t aH = sbase + (c % NSTAGE) * STAGE_BYTES;
        const uint32_t aL = aH + TILE_BYTES;
        const uint32_t bH = aH + 2 * TILE_BYTES;
        const uint32_t bL = aH + 3 * TILE_BYTES;

#pragma unroll
        for (int ks = 0; ks < 4; ks++) {
            const uint32_t kpA = (uint32_t)(ks * 32 + khiA) ^ kxor;
            const uint32_t kpB = (uint32_t)(ks * 32 + khiB) ^ kxor;
            uint32_t ah[4][4], al[4][4];
#pragma unroll
            for (int i = 0; i < 4; i++) {
                ldsm_x4(ah[i], aH + rowA[i] + kpA);
                ldsm_x4(al[i], aL + rowA[i] + kpA);
            }
            uint32_t bh[2][4], bl[2][4];      // [j2][ frag j=2*j2 (0,1) | j=2*j2+1 (2,3) ]
#pragma unroll
            for (int j2 = 0; j2 < 2; j2++) {
                ldsm_x4(bh[j2], bH + rowB4[j2] + kpB);
                ldsm_x4(bl[j2], bL + rowB4[j2] + kpB);
            }
#pragma unroll
            for (int j = 0; j < 4; j++) {
                const uint32_t* pbh = &bh[j >> 1][(j & 1) * 2];
                const uint32_t* pbl = &bl[j >> 1][(j & 1) * 2];
#pragma unroll
                for (int i = 0; i < 4; i++) {
                    mma_bf16(acc[i][j], ah[i], pbh);
                    mma_bf16(acc[i][j], ah[i], pbl);
                    mma_bf16(acc[i][j], al[i], pbh);
                }
            }
        }
    }

    // epilogue: direct global stores (float2 per half-fragment)
    const int qr = lane >> 2;
    const int qc = (lane & 3) * 2;
#pragma unroll
    for (int i = 0; i < 4; i++) {
        const int r0 = m0 + wm * 64 + i * 16 + qr;
#pragma unroll
        for (int j = 0; j < 4; j++) {
            const int nn = n0 + wn * 32 + j * 8 + qc;
            if (nn < Nc) {
                float2 v0 = make_float2(acc[i][j][0], acc[i][j][1]);
                float2 v1 = make_float2(acc[i][j][2], acc[i][j][3]);
                if (EPI == 1) {
                    const float b0 = bias[nn], b1 = bias[nn + 1];
                    v0.x = softplusf(v0.x + b0); v0.y = softplusf(v0.y + b1);
                    v1.x = softplusf(v1.x + b0); v1.y = softplusf(v1.y + b1);
                }
                *(float2*)(C + (size_t)r0 * ldc + nn)       = v0;
                *(float2*)(C + (size_t)(r0 + 8) * ldc + nn) = v1;
            }
        }
    }
}

// ---------------------------------------------------------------------------
// split-K reduce for x_proj: sp = sum(partials); also emit bf16 hi/lo for dt GEMM
// ---------------------------------------------------------------------------
__global__ void xp_reduce(const float* __restrict__ part,
                          float* __restrict__ sp,
                          __nv_bfloat16* __restrict__ sph,
                          __nv_bfloat16* __restrict__ spl)
{
    const int n4 = BL * SP_W / 4;
    int i = blockIdx.x * blockDim.x + threadIdx.x;
    if (i >= n4) return;
    float4 a = ((const float4*)part)[i];
#pragma unroll
    for (int p = 1; p < XP_SPLIT; p++) {
        float4 b = ((const float4*)part)[i + (size_t)p * n4];
        a.x += b.x; a.y += b.y; a.z += b.z; a.w += b.w;
    }
    ((float4*)sp)[i] = a;
    __nv_bfloat162 h0 = __floats2bfloat162_rn(a.x, a.y);
    __nv_bfloat162 h1 = __floats2bfloat162_rn(a.z, a.w);
    __nv_bfloat162 l0 = __floats2bfloat162_rn(a.x - __low2float(h0), a.y - __high2float(h0));
    __nv_bfloat162 l1 = __floats2bfloat162_rn(a.z - __low2float(h1), a.w - __high2float(h1));
    ((__nv_bfloat162*)sph)[2 * i]     = h0;
    ((__nv_bfloat162*)sph)[2 * i + 1] = h1;
    ((__nv_bfloat162*)spl)[2 * i]     = l0;
    ((__nv_bfloat162*)spl)[2 * i + 1] = l1;
}

// ---------------------------------------------------------------------------
// Depthwise causal conv1d (K=4) + bias + silu -> bf16 hi/lo
// ---------------------------------------------------------------------------
__global__ void conv_silu_kernel(const float* __restrict__ proj,
                                 const float* __restrict__ cw,
                                 const float* __restrict__ cb,
                                 __nv_bfloat16* __restrict__ uh,
                                 __nv_bfloat16* __restrict__ ul)
{
    const int idx = blockIdx.x * blockDim.x + threadIdx.x;
    if (idx >= BL * DDIM) return;
    const int d  = idx & (DDIM - 1);
    const int bl = idx >> 12;
    const int l  = bl & (LSEQ - 1);

    const float4 w = *(const float4*)(cw + d * 4);
    const float* base = proj + (size_t)bl * P2D + d;
    float acc = cb[d];
    if (l >= 3) acc = fmaf(w.x, base[-3 * P2D], acc);
    if (l >= 2) acc = fmaf(w.y, base[-2 * P2D], acc);
    if (l >= 1) acc = fmaf(w.z, base[-1 * P2D], acc);
    acc = fmaf(w.w, base[0], acc);
    const float v = siluf(acc);
    const __nv_bfloat16 h = __float2bfloat16(v);
    uh[idx] = h;
    ul[idx] = __float2bfloat16(v - __bfloat162float(h));
}

// ---------------------------------------------------------------------------
// Selective scan (state-in-register, shfl reduction, fused gate epilogue)
// ---------------------------------------------------------------------------
__global__ void __launch_bounds__(256)
scan_kernel(const float* __restrict__ dtg,          // [BL, D]
            const __nv_bfloat16* __restrict__ uhg,  // [BL, D]
            const __nv_bfloat16* __restrict__ ulg,  // [BL, D]
            const float* __restrict__ spg,          // [BL, 160]
            const float* __restrict__ Alog,         // [D, 16]
            const float* __restrict__ Dp,           // [D]
            const float* __restrict__ proj,         // [BL, 8192] gate at D+d
            __nv_bfloat16* __restrict__ yh,
            __nv_bfloat16* __restrict__ yl)
{
    const int b   = blockIdx.y;
    const int d0  = blockIdx.x * 16;
    const int t   = threadIdx.x;
    const int seq = t >> 4;
    const int n   = t & 15;
    const int d   = d0 + seq;

    __shared__ float sdt[64][16];
    __shared__ float su [64][16];
    __shared__ float sB [64][16];
    __shared__ float sC [64][16];
    __shared__ float sy [64][16];

    const float a = -__expf(Alog[d * NSTATE + n]);
    float s = 0.f;

    const int i16 = t >> 4, j16 = t & 15;
    const int i32 = t >> 5, j32 = t & 31;

    for (int l0 = 0; l0 < LSEQ; l0 += 64) {
        const int bl0 = b * LSEQ + l0;
#pragma unroll
        for (int r = 0; r < 4; r++) {
            const int ii = i16 + r * 16;
            const size_t off = (size_t)(bl0 + ii) * DDIM + d0 + j16;
            sdt[ii][j16] = dtg[off];
            su [ii][j16] = __bfloat162float(uhg[off]) + __bfloat162float(ulg[off]);
        }
#pragma unroll
        for (int r = 0; r < 8; r++) {
            const int ii = i32 + r * 8;
            const float v = spg[(size_t)(bl0 + ii) * SP_W + RRANK + j32];
            if (j32 < 16) sB[ii][j32] = v;
            else          sC[ii][j32 - 16] = v;
        }
        __syncthreads();

#pragma unroll 4
        for (int il = 0; il < 64; il++) {
            const float dtv = sdt[il][seq];
            const float dA  = __expf(a * dtv);
            const float dBu = dtv * sB[il][n] * su[il][seq];
            s = fmaf(dA, s, dBu);
            float p = s * sC[il][n];
            p += __shfl_xor_sync(0xffffffffu, p, 8);
            p += __shfl_xor_sync(0xffffffffu, p, 4);
            p += __shfl_xor_sync(0xffffffffu, p, 2);
            p += __shfl_xor_sync(0xffffffffu, p, 1);
            if (n == 0) sy[il][seq] = p;
        }
        __syncthreads();

#pragma unroll
        for (int r = 0; r < 4; r++) {
            const int ii = i16 + r * 16;
            const float yy = sy[ii][j16];
            const float uu = su[ii][j16];
            const float g  = proj[(size_t)(bl0 + ii) * P2D + DDIM + d0 + j16];
            const float yf = fmaf(uu, Dp[d0 + j16], yy) * siluf(g);
            const size_t off = (size_t)(bl0 + ii) * DDIM + d0 + j16;
            const __nv_bfloat16 h = __float2bfloat16(yf);
            yh[off] = h;
            yl[off] = __float2bfloat16(yf - __bfloat162float(h));
        }
        __syncthreads();
    }
}

// ---------------------------------------------------------------------------
// Launch sequence (graph-capturable: kernel launches only)
// ---------------------------------------------------------------------------
extern "C" void kernel_launch(void* const* d_in, const int* in_sizes, int n_in,
                              void* d_out, int out_size)
{
    const float* hs   = (const float*)d_in[0];  // [B,L,H]
    const float* w_in = (const float*)d_in[1];  // [2D,H]
    const float* cw   = (const float*)d_in[2];  // [D,1,K]
    const float* cb   = (const float*)d_in[3];  // [D]
    const float* w_x  = (const float*)d_in[4];  // [160,D]
    const float* w_dt = (const float*)d_in[5];  // [D,R]
    const float* b_dt = (const float*)d_in[6];  // [D]
    const float* alog = (const float*)d_in[7];  // [D,N]
    const float* dpar = (const float*)d_in[8];  // [D]
    const float* w_o  = (const float*)d_in[9];  // [H,D]
    float* out = (float*)d_out;                 // [B,L,H]

    float *proj, *sp, *dtb, *xpp;
    __nv_bfloat16 *hs_h, *hs_l, *win_h, *win_l, *u_h, *u_l, *wx_h, *wx_l;
    __nv_bfloat16 *sp_h, *sp_l, *wdt_h, *wdt_l, *y_h, *y_l, *wo_h, *wo_l;
    cudaGetSymbolAddress((void**)&proj,  g_proj);
    cudaGetSymbolAddress((void**)&sp,    g_sp);
    cudaGetSymbolAddress((void**)&dtb,   g_dt);
    cudaGetSymbolAddress((void**)&xpp,   g_xpp);
    cudaGetSymbolAddress((void**)&hs_h,  g_hs_h);  cudaGetSymbolAddress((void**)&hs_l,  g_hs_l);
    cudaGetSymbolAddress((void**)&win_h, g_win_h); cudaGetSymbolAddress((void**)&win_l, g_win_l);
    cudaGetSymbolAddress((void**)&u_h,   g_u_h);   cudaGetSymbolAddress((void**)&u_l,   g_u_l);
    cudaGetSymbolAddress((void**)&wx_h,  g_wx_h);  cudaGetSymbolAddress((void**)&wx_l,  g_wx_l);
    cudaGetSymbolAddress((void**)&sp_h,  g_sp_h);  cudaGetSymbolAddress((void**)&sp_l,  g_sp_l);
    cudaGetSymbolAddress((void**)&wdt_h, g_wdt_h); cudaGetSymbolAddress((void**)&wdt_l, g_wdt_l);
    cudaGetSymbolAddress((void**)&y_h,   g_y_h);   cudaGetSymbolAddress((void**)&y_l,   g_y_l);
    cudaGetSymbolAddress((void**)&wo_h,  g_wo_h);  cudaGetSymbolAddress((void**)&wo_l,  g_wo_l);

    cudaFuncSetAttribute(tgemm<0>, cudaFuncAttributeMaxDynamicSharedMemorySize, DYN_SMEM);
    cudaFuncSetAttribute(tgemm<1>, cudaFuncAttributeMaxDynamicSharedMemorySize, DYN_SMEM);

    // 0) all fp32 -> bf16 hi/lo conversions in ONE launch
    cvt_all<<<(CVT_N4 + 255) / 256, 256>>>(
        hs, hs_h, hs_l, w_in, win_h, win_l, w_x, wx_h, wx_l,
        w_dt, wdt_h, wdt_l, w_o, wo_h, wo_l);

    // 1) in_proj: proj[2048, 8192] = hs @ w_in^T
    tgemm<0><<<dim3(P2D / 128, BL / 128, 1), 256, DYN_SMEM>>>(
        hs_h, hs_l, HDIM, win_h, win_l, HDIM, proj, P2D, P2D, HDIM, nullptr, 0);

    // 2) conv + silu -> u (hi/lo)
    conv_silu_kernel<<<(BL * DDIM) / 256, 256>>>(proj, cw, cb, u_h, u_l);

    // 3) x_proj split-K: partials[8][2048, 160] = u @ w_x^T (K slices of 512)
    tgemm<0><<<dim3(2, BL / 128, XP_SPLIT), 256, DYN_SMEM>>>(
        u_h, u_l, DDIM, wx_h, wx_l, DDIM, xpp, SP_W, SP_W, XP_KLEN,
        nullptr, (size_t)BL * SP_W);

    // 3b) reduce partials -> sp (fp32) + sp hi/lo (bf16)
    xp_reduce<<<(BL * SP_W / 4 + 255) / 256, 256>>>(xpp, sp, sp_h, sp_l);

    // 4) dt_proj + bias + softplus: dt[2048, 4096]
    tgemm<1><<<dim3(DDIM / 128, BL / 128, 1), 256, DYN_SMEM>>>(
        sp_h, sp_l, SP_W, wdt_h, wdt_l, RRANK, dtb, DDIM, DDIM, RRANK, b_dt, 0);

    // 5) selective scan + D-skip + gate (fused) -> y (hi/lo)
    scan_kernel<<<dim3(DDIM / 16, BSZ), 256>>>(dtb, u_h, u_l, sp, alog, dpar, proj, y_h, y_l);

    // 6) out_proj: out[2048, 2048] = y @ w_o^T
    tgemm<0><<<dim3(HDIM / 128, BL / 128, 1), 256, DYN_SMEM>>>(
        y_h, y_l, DDIM, wo_h, wo_l, DDIM, out, HDIM, HDIM, DDIM, nullptr, 0);
}

// round 5
// speedup vs baseline: 2.9694x; 1.0144x over previous
#include <cuda_runtime.h>
#include <cuda_bf16.h>
#include <math.h>
#include <stdint.h>

// Problem constants (fixed by setup_inputs)
#define BSZ    2
#define LSEQ   1024
#define HDIM   2048
#define DDIM   4096
#define NSTATE 16
#define RRANK  128
#define KCONV  4
#define BL     (BSZ * LSEQ)          // 2048 rows
#define P2D    (2 * DDIM)            // 8192
#define SP_W   (RRANK + 2 * NSTATE)  // 160
#define XP_SPLIT 8                   // split-K factor for x_proj
#define XP_KLEN  (DDIM / XP_SPLIT)   // 512

// ---------------------------------------------------------------------------
// Scratch: static device globals (no cudaMalloc allowed)
// ---------------------------------------------------------------------------
__device__ float g_proj[(size_t)BL * P2D];     // in_proj output [BL, 8192] (u | gate)
__device__ float g_sp  [(size_t)BL * SP_W];    // x_proj output [BL, 160]
__device__ float g_dt  [(size_t)BL * DDIM];    // softplus(dt_proj) [BL, D]
__device__ float g_xpp [(size_t)XP_SPLIT * BL * SP_W];  // split-K partials

// bf16 hi/lo split buffers
__device__ __nv_bfloat16 g_hs_h[(size_t)BL * HDIM],  g_hs_l[(size_t)BL * HDIM];
__device__ __nv_bfloat16 g_win_h[(size_t)P2D * HDIM], g_win_l[(size_t)P2D * HDIM];
__device__ __nv_bfloat16 g_u_h[(size_t)BL * DDIM],   g_u_l[(size_t)BL * DDIM];
__device__ __nv_bfloat16 g_wx_h[(size_t)SP_W * DDIM], g_wx_l[(size_t)SP_W * DDIM];
__device__ __nv_bfloat16 g_sp_h[(size_t)BL * SP_W],  g_sp_l[(size_t)BL * SP_W];
__device__ __nv_bfloat16 g_wdt_h[(size_t)DDIM * RRANK], g_wdt_l[(size_t)DDIM * RRANK];
__device__ __nv_bfloat16 g_y_h[(size_t)BL * DDIM],   g_y_l[(size_t)BL * DDIM];
__device__ __nv_bfloat16 g_wo_h[(size_t)HDIM * DDIM], g_wo_l[(size_t)HDIM * DDIM];

__device__ __forceinline__ float softplusf(float x) {
    return (x > 20.f) ? x : log1pf(__expf(x));
}
__device__ __forceinline__ float siluf(float x) {
    return x / (1.f + __expf(-x));
}

// ---------------------------------------------------------------------------
// PTX helpers (sm_80+ portable: cp.async / ldmatrix / mma.sync)
// ---------------------------------------------------------------------------
__device__ __forceinline__ uint32_t smem_u32(const void* p) {
    uint32_t a;
    asm("{ .reg .u64 t; cvta.to.shared.u64 t, %1; cvt.u32.u64 %0, t; }" : "=r"(a) : "l"(p));
    return a;
}
__device__ __forceinline__ void cpa16(uint32_t dst, const void* src, int sz) {
    asm volatile("cp.async.cg.shared.global [%0], [%1], 16, %2;"
                 :: "r"(dst), "l"(src), "r"(sz) : "memory");
}
__device__ __forceinline__ void cpa16f(uint32_t dst, const void* src) {
    asm volatile("cp.async.cg.shared.global [%0], [%1], 16;"
                 :: "r"(dst), "l"(src) : "memory");
}
__device__ __forceinline__ void cpa_commit() {
    asm volatile("cp.async.commit_group;" ::: "memory");
}
template <int N>
__device__ __forceinline__ void cpa_wait() {
    asm volatile("cp.async.wait_group %0;" :: "n"(N) : "memory");
}
__device__ __forceinline__ void ldsm_x4(uint32_t* r, uint32_t addr) {
    asm volatile("ldmatrix.sync.aligned.m8n8.x4.shared.b16 {%0,%1,%2,%3}, [%4];"
                 : "=r"(r[0]), "=r"(r[1]), "=r"(r[2]), "=r"(r[3]) : "r"(addr));
}
__device__ __forceinline__ void mma_bf16(float* c, const uint32_t* a, const uint32_t* b) {
    asm volatile(
        "mma.sync.aligned.m16n8k16.row.col.f32.bf16.bf16.f32 "
        "{%0,%1,%2,%3}, {%4,%5,%6,%7}, {%8,%9}, {%0,%1,%2,%3};"
        : "+f"(c[0]), "+f"(c[1]), "+f"(c[2]), "+f"(c[3])
        : "r"(a[0]), "r"(a[1]), "r"(a[2]), "r"(a[3]), "r"(b[0]), "r"(b[1]));
}

// ---------------------------------------------------------------------------
// Merged fp32 -> bf16 hi/lo split for all 5 weight/input tensors (1 launch)
// ---------------------------------------------------------------------------
#define CVT_N0 (BL * HDIM / 4)                       // hs
#define CVT_N1 (CVT_N0 + P2D * HDIM / 4)             // + w_in
#define CVT_N2 (CVT_N1 + SP_W * DDIM / 4)            // + w_x
#define CVT_N3 (CVT_N2 + DDIM * RRANK / 4)           // + w_dt
#define CVT_N4 (CVT_N3 + HDIM * DDIM / 4)            // + w_o

__device__ __forceinline__ void cvt_one(const float* __restrict__ x,
                                        __nv_bfloat16* __restrict__ h,
                                        __nv_bfloat16* __restrict__ l, int i)
{
    float4 v = ((const float4*)x)[i];
    __nv_bfloat162 h0 = __floats2bfloat162_rn(v.x, v.y);
    __nv_bfloat162 h1 = __floats2bfloat162_rn(v.z, v.w);
    __nv_bfloat162 l0 = __floats2bfloat162_rn(v.x - __low2float(h0), v.y - __high2float(h0));
    __nv_bfloat162 l1 = __floats2bfloat162_rn(v.z - __low2float(h1), v.w - __high2float(h1));
    ((__nv_bfloat162*)h)[2 * i]     = h0;
    ((__nv_bfloat162*)h)[2 * i + 1] = h1;
    ((__nv_bfloat162*)l)[2 * i]     = l0;
    ((__nv_bfloat162*)l)[2 * i + 1] = l1;
}

__global__ void cvt_all(const float* s0, __nv_bfloat16* h0, __nv_bfloat16* l0,
                        const float* s1, __nv_bfloat16* h1, __nv_bfloat16* l1,
                        const float* s2, __nv_bfloat16* h2, __nv_bfloat16* l2,
                        const float* s3, __nv_bfloat16* h3, __nv_bfloat16* l3,
                        const float* s4, __nv_bfloat16* h4, __nv_bfloat16* l4)
{
    int i = blockIdx.x * blockDim.x + threadIdx.x;
    if (i < CVT_N0)      cvt_one(s0, h0, l0, i);
    else if (i < CVT_N1) cvt_one(s1, h1, l1, i - CVT_N0);
    else if (i < CVT_N2) cvt_one(s2, h2, l2, i - CVT_N1);
    else if (i < CVT_N3) cvt_one(s3, h3, l3, i - CVT_N2);
    else if (i < CVT_N4) cvt_one(s4, h4, l4, i - CVT_N3);
}

// ---------------------------------------------------------------------------
// Tensor-core split-bf16 GEMM:  C[m,n] = sum_k A[m,k]*Bw[n,k]
//   A ~ Ah+Al, Bw ~ Bh+Bl (bf16);  C = Ah*Bh + Ah*Bl + Al*Bh (fp32 acc)
// 128x128 CTA tile, BK=32, 8 warps (2x4), 3-stage cp.async pipeline,
// 96KB smem + <=128 regs  =>  2 CTAs/SM (4 warps/SMSP for latency hiding).
// Tile rows are 64B (32 bf16) with SW64-style swizzle:
//   sw(off) = off ^ ((off>>3) & 0x30)   (XOR k-chunk bits with row-pair bits)
// EPI==1: C = softplus(C + bias[n]).  GUARD: predicate B rows by Nc.
// ---------------------------------------------------------------------------
#define TILE_BYTES  8192                 // 128 rows x 64B
#define STAGE_BYTES (4 * TILE_BYTES)     // Ah | Al | Bh | Bl = 32KB
#define NSTAGE      3
#define DYN_SMEM    (NSTAGE * STAGE_BYTES)   // 96KB

template <bool GUARD>
__device__ __forceinline__ void load_tile_async(
    const __nv_bfloat16* __restrict__ src, int ld, int row0, int k0,
    uint32_t dstbase, int tid, int nrows)
{
#pragma unroll
    for (int i = 0; i < 2; i++) {
        const int u   = tid + i * 256;        // 0..511
        const int row = u >> 2;               // 0..127
        const int s   = u & 3;                // 16B seg in 64B row
        const uint32_t off = (uint32_t)(row * 64 + ((s * 16) ^ ((row & 6) << 3)));
        if (GUARD) {
            const int ok = (row0 + row) < nrows;
            const void* p = src + (size_t)(row0 + (ok ? row : 0)) * ld + k0 + s * 8;
            cpa16(dstbase + off, p, ok ? 16 : 0);
        } else {
            cpa16f(dstbase + off, src + (size_t)(row0 + row) * ld + k0 + s * 8);
        }
    }
}

template <int EPI, bool GUARD>
__global__ void __launch_bounds__(256, 2)
tgemm(const __nv_bfloat16* __restrict__ Ah, const __nv_bfloat16* __restrict__ Al, int lda,
      const __nv_bfloat16* __restrict__ Bh, const __nv_bfloat16* __restrict__ Bl, int ldb,
      float* __restrict__ C, int ldc, int Nc, int klen,
      const float* __restrict__ bias, size_t partStride)
{
    extern __shared__ __align__(1024) char smem[];
    const uint32_t sbase = smem_u32(smem);

    const int tid  = threadIdx.x;
    const int wid  = tid >> 5;
    const int lane = tid & 31;
    const int m0   = blockIdx.y * 128;
    const int n0   = blockIdx.x * 128;
    const int kb   = blockIdx.z * klen;
    C += (size_t)blockIdx.z * partStride;
    const int wm   = wid >> 2;             // 0..1 -> 64-row slab
    const int wn   = wid & 3;              // 0..3 -> 32-col slab

    // ldmatrix per-lane addressing: row byte offset + per-row swizzle XOR
    const uint32_t khiA = (uint32_t)((lane >> 4) * 16);          // A k-half select
    const uint32_t khiB = (uint32_t)(((lane >> 3) & 1) * 16);    // B k-half select
    uint32_t pA[4], xA[4], pB[2], xB[2];
#pragma unroll
    for (int i = 0; i < 4; i++) {
        const int r = wm * 64 + i * 16 + (lane & 15);
        pA[i] = (uint32_t)(r * 64);
        xA[i] = (uint32_t)((r & 6) << 3);
    }
#pragma unroll
    for (int j2 = 0; j2 < 2; j2++) {
        const int r = wn * 32 + j2 * 16 + ((lane >> 4) << 3) + (lane & 7);
        pB[j2] = (uint32_t)(r * 64);
        xB[j2] = (uint32_t)((r & 6) << 3);
    }

    float acc[4][4][4];
#pragma unroll
    for (int i = 0; i < 4; i++)
#pragma unroll
        for (int j = 0; j < 4; j++)
#pragma unroll
            for (int r = 0; r < 4; r++) acc[i][j][r] = 0.f;

    const int nch = klen >> 5;

    // prologue: stages 0 .. NSTAGE-2 (always-commit for uniform wait counts)
#pragma unroll
    for (int s = 0; s < NSTAGE - 1; s++) {
        if (s < nch) {
            uint32_t st = sbase + s * STAGE_BYTES;
            const int k0 = kb + (s << 5);
            load_tile_async<false>(Ah, lda, m0, k0, st,                  tid, 0);
            load_tile_async<false>(Al, lda, m0, k0, st + TILE_BYTES,     tid, 0);
            load_tile_async<GUARD>(Bh, ldb, n0, k0, st + 2 * TILE_BYTES, tid, Nc);
            load_tile_async<GUARD>(Bl, ldb, n0, k0, st + 3 * TILE_BYTES, tid, Nc);
        }
        cpa_commit();
    }

    for (int c = 0; c < nch; c++) {
        cpa_wait<NSTAGE - 2>();
        __syncthreads();

        // prefetch stage c+NSTAGE-1 (buffer freed at iter c-1)
        const int cp = c + NSTAGE - 1;
        if (cp < nch) {
            uint32_t st = sbase + (cp % NSTAGE) * STAGE_BYTES;
            const int k0 = kb + (cp << 5);
            load_tile_async<false>(Ah, lda, m0, k0, st,                  tid, 0);
            load_tile_async<false>(Al, lda, m0, k0, st + TILE_BYTES,     tid, 0);
            load_tile_async<GUARD>(Bh, ldb, n0, k0, st + 2 * TILE_BYTES, tid, Nc);
            load_tile_async<GUARD>(Bl, ldb, n0, k0, st + 3 * TILE_BYTES, tid, Nc);
        }
        cpa_commit();

        const uint32_t aH = sbase + (c % NSTAGE) * STAGE_BYTES;
        const uint32_t aL = aH + TILE_BYTES;
        const uint32_t bH = aH + 2 * TILE_BYTES;
        const uint32_t bL = aH + 3 * TILE_BYTES;

#pragma unroll
        for (int ks = 0; ks < 2; ks++) {
            const uint32_t kA = (uint32_t)(ks * 32) + khiA;
            const uint32_t kB = (uint32_t)(ks * 32) + khiB;
            uint32_t ah[4][4], al[4][4];
#pragma unroll
            for (int i = 0; i < 4; i++) {
                ldsm_x4(ah[i], aH + pA[i] + (kA ^ xA[i]));
                ldsm_x4(al[i], aL + pA[i] + (kA ^ xA[i]));
            }
            uint32_t bh[2][4], bl[2][4];
#pragma unroll
            for (int j2 = 0; j2 < 2; j2++) {
                ldsm_x4(bh[j2], bH + pB[j2] + (kB ^ xB[j2]));
                ldsm_x4(bl[j2], bL + pB[j2] + (kB ^ xB[j2]));
            }
#pragma unroll
            for (int j = 0; j < 4; j++) {
                const uint32_t* pbh = &bh[j >> 1][(j & 1) * 2];
                const uint32_t* pbl = &bl[j >> 1][(j & 1) * 2];
#pragma unroll
                for (int i = 0; i < 4; i++) {
                    mma_bf16(acc[i][j], ah[i], pbh);
                    mma_bf16(acc[i][j], ah[i], pbl);
                    mma_bf16(acc[i][j], al[i], pbh);
                }
            }
        }
    }

    // epilogue: direct global stores (float2 per half-fragment)
    const int qr = lane >> 2;
    const int qc = (lane & 3) * 2;
#pragma unroll
    for (int i = 0; i < 4; i++) {
        const int r0 = m0 + wm * 64 + i * 16 + qr;
#pragma unroll
        for (int j = 0; j < 4; j++) {
            const int nn = n0 + wn * 32 + j * 8 + qc;
            if (!GUARD || nn < Nc) {
                float2 v0 = make_float2(acc[i][j][0], acc[i][j][1]);
                float2 v1 = make_float2(acc[i][j][2], acc[i][j][3]);
                if (EPI == 1) {
                    const float b0 = bias[nn], b1 = bias[nn + 1];
                    v0.x = softplusf(v0.x + b0); v0.y = softplusf(v0.y + b1);
                    v1.x = softplusf(v1.x + b0); v1.y = softplusf(v1.y + b1);
                }
                *(float2*)(C + (size_t)r0 * ldc + nn)       = v0;
                *(float2*)(C + (size_t)(r0 + 8) * ldc + nn) = v1;
            }
        }
    }
}

// ---------------------------------------------------------------------------
// split-K reduce for x_proj: sp = sum(partials); also emit bf16 hi/lo for dt GEMM
// ---------------------------------------------------------------------------
__global__ void xp_reduce(const float* __restrict__ part,
                          float* __restrict__ sp,
                          __nv_bfloat16* __restrict__ sph,
                          __nv_bfloat16* __restrict__ spl)
{
    const int n4 = BL * SP_W / 4;
    int i = blockIdx.x * blockDim.x + threadIdx.x;
    if (i >= n4) return;
    float4 a = ((const float4*)part)[i];
#pragma unroll
    for (int p = 1; p < XP_SPLIT; p++) {
        float4 b = ((const float4*)part)[i + (size_t)p * n4];
        a.x += b.x; a.y += b.y; a.z += b.z; a.w += b.w;
    }
    ((float4*)sp)[i] = a;
    __nv_bfloat162 h0 = __floats2bfloat162_rn(a.x, a.y);
    __nv_bfloat162 h1 = __floats2bfloat162_rn(a.z, a.w);
    __nv_bfloat162 l0 = __floats2bfloat162_rn(a.x - __low2float(h0), a.y - __high2float(h0));
    __nv_bfloat162 l1 = __floats2bfloat162_rn(a.z - __low2float(h1), a.w - __high2float(h1));
    ((__nv_bfloat162*)sph)[2 * i]     = h0;
    ((__nv_bfloat162*)sph)[2 * i + 1] = h1;
    ((__nv_bfloat162*)spl)[2 * i]     = l0;
    ((__nv_bfloat162*)spl)[2 * i + 1] = l1;
}

// ---------------------------------------------------------------------------
// Depthwise causal conv1d (K=4) + bias + silu -> bf16 hi/lo
// ---------------------------------------------------------------------------
__global__ void conv_silu_kernel(const float* __restrict__ proj,
                                 const float* __restrict__ cw,
                                 const float* __restrict__ cb,
                                 __nv_bfloat16* __restrict__ uh,
                                 __nv_bfloat16* __restrict__ ul)
{
    const int idx = blockIdx.x * blockDim.x + threadIdx.x;
    if (idx >= BL * DDIM) return;
    const int d  = idx & (DDIM - 1);
    const int bl = idx >> 12;
    const int l  = bl & (LSEQ - 1);

    const float4 w = *(const float4*)(cw + d * 4);
    const float* base = proj + (size_t)bl * P2D + d;
    float acc = cb[d];
    if (l >= 3) acc = fmaf(w.x, base[-3 * P2D], acc);
    if (l >= 2) acc = fmaf(w.y, base[-2 * P2D], acc);
    if (l >= 1) acc = fmaf(w.z, base[-1 * P2D], acc);
    acc = fmaf(w.w, base[0], acc);
    const float v = siluf(acc);
    const __nv_bfloat16 h = __float2bfloat16(v);
    uh[idx] = h;
    ul[idx] = __float2bfloat16(v - __bfloat162float(h));
}

// ---------------------------------------------------------------------------
// Selective scan (state-in-register, shfl reduction, fused gate epilogue)
// ---------------------------------------------------------------------------
__global__ void __launch_bounds__(256)
scan_kernel(const float* __restrict__ dtg,          // [BL, D]
            const __nv_bfloat16* __restrict__ uhg,  // [BL, D]
            const __nv_bfloat16* __restrict__ ulg,  // [BL, D]
            const float* __restrict__ spg,          // [BL, 160]
            const float* __restrict__ Alog,         // [D, 16]
            const float* __restrict__ Dp,           // [D]
            const float* __restrict__ proj,         // [BL, 8192] gate at D+d
            __nv_bfloat16* __restrict__ yh,
            __nv_bfloat16* __restrict__ yl)
{
    const int b   = blockIdx.y;
    const int d0  = blockIdx.x * 16;
    const int t   = threadIdx.x;
    const int seq = t >> 4;
    const int n   = t & 15;
    const int d   = d0 + seq;

    __shared__ float sdt[64][16];
    __shared__ float su [64][16];
    __shared__ float sB [64][16];
    __shared__ float sC [64][16];
    __shared__ float sy [64][16];

    const float a = -__expf(Alog[d * NSTATE + n]);
    float s = 0.f;

    const int i16 = t >> 4, j16 = t & 15;
    const int i32 = t >> 5, j32 = t & 31;

    for (int l0 = 0; l0 < LSEQ; l0 += 64) {
        const int bl0 = b * LSEQ + l0;
#pragma unroll
        for (int r = 0; r < 4; r++) {
            const int ii = i16 + r * 16;
            const size_t off = (size_t)(bl0 + ii) * DDIM + d0 + j16;
            sdt[ii][j16] = dtg[off];
            su [ii][j16] = __bfloat162float(uhg[off]) + __bfloat162float(ulg[off]);
        }
#pragma unroll
        for (int r = 0; r < 8; r++) {
            const int ii = i32 + r * 8;
            const float v = spg[(size_t)(bl0 + ii) * SP_W + RRANK + j32];
            if (j32 < 16) sB[ii][j32] = v;
            else          sC[ii][j32 - 16] = v;
        }
        __syncthreads();

#pragma unroll 4
        for (int il = 0; il < 64; il++) {
            const float dtv = sdt[il][seq];
            const float dA  = __expf(a * dtv);
            const float dBu = dtv * sB[il][n] * su[il][seq];
            s = fmaf(dA, s, dBu);
            float p = s * sC[il][n];
            p += __shfl_xor_sync(0xffffffffu, p, 8);
            p += __shfl_xor_sync(0xffffffffu, p, 4);
            p += __shfl_xor_sync(0xffffffffu, p, 2);
            p += __shfl_xor_sync(0xffffffffu, p, 1);
            if (n == 0) sy[il][seq] = p;
        }
        __syncthreads();

#pragma unroll
        for (int r = 0; r < 4; r++) {
            const int ii = i16 + r * 16;
            const float yy = sy[ii][j16];
            const float uu = su[ii][j16];
            const float g  = proj[(size_t)(bl0 + ii) * P2D + DDIM + d0 + j16];
            const float yf = fmaf(uu, Dp[d0 + j16], yy) * siluf(g);
            const size_t off = (size_t)(bl0 + ii) * DDIM + d0 + j16;
            const __nv_bfloat16 h = __float2bfloat16(yf);
            yh[off] = h;
            yl[off] = __float2bfloat16(yf - __bfloat162float(h));
        }
        __syncthreads();
    }
}

// ---------------------------------------------------------------------------
// Launch sequence (graph-capturable: kernel launches only)
// ---------------------------------------------------------------------------
extern "C" void kernel_launch(void* const* d_in, const int* in_sizes, int n_in,
                              void* d_out, int out_size)
{
    const float* hs   = (const float*)d_in[0];  // [B,L,H]
    const float* w_in = (const float*)d_in[1];  // [2D,H]
    const float* cw   = (const float*)d_in[2];  // [D,1,K]
    const float* cb   = (const float*)d_in[3];  // [D]
    const float* w_x  = (const float*)d_in[4];  // [160,D]
    const float* w_dt = (const float*)d_in[5];  // [D,R]
    const float* b_dt = (const float*)d_in[6];  // [D]
    const float* alog = (const float*)d_in[7];  // [D,N]
    const float* dpar = (const float*)d_in[8];  // [D]
    const float* w_o  = (const float*)d_in[9];  // [H,D]
    float* out = (float*)d_out;                 // [B,L,H]

    float *proj, *sp, *dtb, *xpp;
    __nv_bfloat16 *hs_h, *hs_l, *win_h, *win_l, *u_h, *u_l, *wx_h, *wx_l;
    __nv_bfloat16 *sp_h, *sp_l, *wdt_h, *wdt_l, *y_h, *y_l, *wo_h, *wo_l;
    cudaGetSymbolAddress((void**)&proj,  g_proj);
    cudaGetSymbolAddress((void**)&sp,    g_sp);
    cudaGetSymbolAddress((void**)&dtb,   g_dt);
    cudaGetSymbolAddress((void**)&xpp,   g_xpp);
    cudaGetSymbolAddress((void**)&hs_h,  g_hs_h);  cudaGetSymbolAddress((void**)&hs_l,  g_hs_l);
    cudaGetSymbolAddress((void**)&win_h, g_win_h); cudaGetSymbolAddress((void**)&win_l, g_win_l);
    cudaGetSymbolAddress((void**)&u_h,   g_u_h);   cudaGetSymbolAddress((void**)&u_l,   g_u_l);
    cudaGetSymbolAddress((void**)&wx_h,  g_wx_h);  cudaGetSymbolAddress((void**)&wx_l,  g_wx_l);
    cudaGetSymbolAddress((void**)&sp_h,  g_sp_h);  cudaGetSymbolAddress((void**)&sp_l,  g_sp_l);
    cudaGetSymbolAddress((void**)&wdt_h, g_wdt_h); cudaGetSymbolAddress((void**)&wdt_l, g_wdt_l);
    cudaGetSymbolAddress((void**)&y_h,   g_y_h);   cudaGetSymbolAddress((void**)&y_l,   g_y_l);
    cudaGetSymbolAddress((void**)&wo_h,  g_wo_h);  cudaGetSymbolAddress((void**)&wo_l,  g_wo_l);

    cudaFuncSetAttribute(tgemm<0, false>, cudaFuncAttributeMaxDynamicSharedMemorySize, DYN_SMEM);
    cudaFuncSetAttribute(tgemm<0, true>,  cudaFuncAttributeMaxDynamicSharedMemorySize, DYN_SMEM);
    cudaFuncSetAttribute(tgemm<1, false>, cudaFuncAttributeMaxDynamicSharedMemorySize, DYN_SMEM);

    // 0) all fp32 -> bf16 hi/lo conversions in ONE launch
    cvt_all<<<(CVT_N4 + 255) / 256, 256>>>(
        hs, hs_h, hs_l, w_in, win_h, win_l, w_x, wx_h, wx_l,
        w_dt, wdt_h, wdt_l, w_o, wo_h, wo_l);

    // 1) in_proj: proj[2048, 8192] = hs @ w_in^T
    tgemm<0, false><<<dim3(P2D / 128, BL / 128, 1), 256, DYN_SMEM>>>(
        hs_h, hs_l, HDIM, win_h, win_l, HDIM, proj, P2D, P2D, HDIM, nullptr, 0);

    // 2) conv + silu -> u (hi/lo)
    conv_silu_kernel<<<(BL * DDIM) / 256, 256>>>(proj, cw, cb, u_h, u_l);

    // 3) x_proj split-K: partials[8][2048, 160] = u @ w_x^T (K slices of 512)
    tgemm<0, true><<<dim3(2, BL / 128, XP_SPLIT), 256, DYN_SMEM>>>(
        u_h, u_l, DDIM, wx_h, wx_l, DDIM, xpp, SP_W, SP_W, XP_KLEN,
        nullptr, (size_t)BL * SP_W);

    // 3b) reduce partials -> sp (fp32) + sp hi/lo (bf16)
    xp_reduce<<<(BL * SP_W / 4 + 255) / 256, 256>>>(xpp, sp, sp_h, sp_l);

    // 4) dt_proj + bias + softplus: dt[2048, 4096]
    tgemm<1, false><<<dim3(DDIM / 128, BL / 128, 1), 256, DYN_SMEM>>>(
        sp_h, sp_l, SP_W, wdt_h, wdt_l, RRANK, dtb, DDIM, DDIM, RRANK, b_dt, 0);

    // 5) selective scan + D-skip + gate (fused) -> y (hi/lo)
    scan_kernel<<<dim3(DDIM / 16, BSZ), 256>>>(dtb, u_h, u_l, sp, alog, dpar, proj, y_h, y_l);

    // 6) out_proj: out[2048, 2048] = y @ w_o^T
    tgemm<0, false><<<dim3(HDIM / 128, BL / 128, 1), 256, DYN_SMEM>>>(
        y_h, y_l, DDIM, wo_h, wo_l, DDIM, out, HDIM, HDIM, DDIM, nullptr, 0);
}